// round 8
// baseline (speedup 1.0000x reference)
#include <cuda_runtime.h>

#define D    768
#define NH   12
#define DKH  64
#define TT   16
#define ENCL 256
#define DFF  3072
#define NV   32128
#define NL   4
#define NB   2
#define EPSF 1e-6f
#define RSQRT_D 0.03608439182435161f   // 768^-0.5
#define NBLK 144
#define NTHR 512

// ------------------------------------------------------------------ scratch
__device__ float g_x  [NB*D];
__device__ float g_q  [NB*D];
__device__ float g_q2 [NB*D];
__device__ float g_ff [NB*DFF];
__device__ float g_kc [NL*NB*TT*D];
__device__ float g_vc [NL*NB*TT*D];
__device__ float g_ckt[NL*NB*NH*DKH*ENCL];   // cross K transposed [l][b][h][dk][pos]
__device__ float g_cv [NL*NB*ENCL*D];        // cross V natural
__device__ unsigned long long g_bmax[2*NBLK];
__device__ unsigned g_cnt;

struct Params {
    const float *emb, *ln1, *qw, *kw, *vw, *ow, *ln2, *cqw, *cow, *ln3, *wi, *wo, *fln, *rb;
    float* out;
};

// ------------------------------------------------------------------ counter barrier
__device__ __forceinline__ void g_arrive() {
    __syncthreads();
    if (threadIdx.x == 0)
        asm volatile("red.release.gpu.global.add.u32 [%0], 1;"
                     :: "l"(&g_cnt) : "memory");
}
__device__ __forceinline__ void g_waitbar(unsigned bar) {
    if (threadIdx.x == 0) {
        unsigned tgt = bar * NBLK, v;
        do {
            asm volatile("ld.acquire.gpu.global.u32 %0, [%1];"
                         : "=r"(v) : "l"(&g_cnt) : "memory");
        } while (v < tgt);
    }
    __syncthreads();
}

// ------------------------------------------------------------------ cp.async weight prefetch (evict_first)
__device__ __forceinline__ void pf_tile(const float* __restrict__ W, int Dout,
                                        int row0, int colpos, int R, float* swbuf,
                                        unsigned long long pol)
{
    const float* base = W + (size_t)row0 * Dout + (colpos << 7);
    unsigned sb_ = (unsigned)__cvta_generic_to_shared(swbuf);
    for (int chunk = threadIdx.x; chunk < R * 32; chunk += NTHR) {
        int r = chunk >> 5, c4 = (chunk & 31) << 2;
        asm volatile("cp.async.cg.shared.global.L2::cache_hint [%0], [%1], 16, %2;"
                     :: "r"(sb_ + (unsigned)(((r << 7) + c4) << 2)),
                        "l"(base + (size_t)r * Dout + c4), "l"(pol) : "memory");
    }
    asm volatile("cp.async.commit_group;" ::: "memory");
}

// ------------------------------------------------------------------ fused rms + smem staging of x
// loads x0/x1 (768 each) into sx[0..768) / sx[768..1536), returns rsqrt norms
__device__ __forceinline__ float2 rms_stage(const float* x0, const float* x1,
                                            float* sx, float* sred) {
    float s0 = 0.f, s1 = 0.f;
    for (int i = threadIdx.x; i < D; i += NTHR) {
        float a = __ldcg(x0 + i), b = __ldcg(x1 + i);
        sx[i] = a; sx[D + i] = b;
        s0 += a * a; s1 += b * b;
    }
    #pragma unroll
    for (int o = 16; o; o >>= 1) {
        s0 += __shfl_xor_sync(0xffffffffu, s0, o);
        s1 += __shfl_xor_sync(0xffffffffu, s1, o);
    }
    if ((threadIdx.x & 31) == 0) {
        sred[threadIdx.x >> 5]        = s0;
        sred[16 + (threadIdx.x >> 5)] = s1;
    }
    __syncthreads();
    if (threadIdx.x == 0) {
        float t0 = 0.f, t1 = 0.f;
        #pragma unroll
        for (int w = 0; w < 16; w++) { t0 += sred[w]; t1 += sred[16 + w]; }
        sred[32] = rsqrtf(t0 / (float)D + EPSF);
        sred[33] = rsqrtf(t1 / (float)D + EPSF);
    }
    __syncthreads();
    float2 r; r.x = sred[32]; r.y = sred[33];
    return r;
}

// ------------------------------------------------------------------ smem-weight GEMV (waits 1 pending group)
template <int R>
__device__ __forceinline__ void gemv_dyn(const float* sw,
    const float* sh0, const float* sh1, int colpos, float* part,
    float* o0, float* o1)
{
    asm volatile("cp.async.wait_group 1;" ::: "memory");
    __syncthreads();
    const int tid = threadIdx.x;
    const int cg = tid & 31, bsel = (tid >> 5) & 1, slice = tid >> 6;
    const float* x = (bsel ? sh1 : sh0) + slice * (R / 8);
    const float4* w4 = (const float4*)sw + slice * (R / 8) * 32 + cg;
    float ax = 0.f, ay = 0.f, az = 0.f, aw = 0.f;
    #pragma unroll
    for (int r = 0; r < R / 8; r++) {
        float4 wv = w4[r * 32];
        float xv = x[r];
        ax += xv * wv.x; ay += xv * wv.y; az += xv * wv.z; aw += xv * wv.w;
    }
    ((float4*)part)[tid] = make_float4(ax, ay, az, aw);
    __syncthreads();
    if (tid < 256) {
        int cc = tid & 127, bs = tid >> 7;
        int g = cc >> 2, comp = cc & 3;
        float sum = 0.f;
        #pragma unroll
        for (int sl = 0; sl < 8; sl++)
            sum += part[((sl << 6) + (bs << 5) + g) * 4 + comp];
        atomicAdd((bs ? o1 : o0) + (colpos << 7) + cc, sum);
    }
}

// ------------------------------------------------------------------ persistent decode
__global__ __launch_bounds__(NTHR, 1) void k_decode(Params p) {
    extern __shared__ float dyn[];           // 2 x 16384 floats
    float* buf0 = dyn;
    float* buf1 = dyn + 16384;
    __shared__ float s[2368];                // part/sx s[0..2048) sh0@2048 sh1@2176 sred@2304
    __shared__ unsigned long long sb[32];
    __shared__ int stok[NB];
    float* part = s;
    float* sh0  = s + 2048;
    float* sh1  = s + 2176;
    float* sred = s + 2304;
    const int bx = blockIdx.x, tid = threadIdx.x;
    unsigned bar = 0;
    unsigned long long pol, polL;
    asm volatile("createpolicy.fractional.L2::evict_first.b64 %0, 1.0;" : "=l"(pol));
    asm volatile("createpolicy.fractional.L2::evict_last.b64 %0, 1.0;" : "=l"(polL));

    // ---- init (each replay)
    for (int i = bx * NTHR + tid; i < NL * NB * TT * D; i += NBLK * NTHR) {
        g_kc[i] = 0.f; g_vc[i] = 0.f;
    }
    for (int i = bx * NTHR + tid; i < NB * D; i += NBLK * NTHR) { g_q[i] = 0.f; g_q2[i] = 0.f; }
    for (int i = bx * NTHR + tid; i < NB * DFF; i += NBLK * NTHR) g_ff[i] = 0.f;

    // job decode
    const int mat    = bx / 48;
    const int qrem   = bx % 48;
    const int qcol   = qrem >> 3,  qrow0 = (qrem & 7) * 96;    // qkv tiles
    const int scol   = bx / 24,    srow0 = (bx % 24) * 32;     // o/cq/co tiles
    const int hh     = srow0 >> 6;                              // head for fused attn
    const int wicol  = bx / 6,     wirow0 = (bx % 6) * 128;    // wi tiles
    const int worow0 = (bx % 24) * 128;                        // wo tiles

    // prefetch qkv layer 0 into buf0
    {
        const float* W = (mat == 0 ? p.qw : (mat == 1 ? p.kw : p.vw));
        pf_tile(W, D, qrow0, qcol, 96, buf0, pol);
    }
    g_arrive(); ++bar;

    for (int t = 0; t < TT; t++) {
        for (int l = 0; l < NL; l++) {
            const size_t MO = (size_t)l * D * D;
            float* kcb = g_kc + ((size_t)(l * NB) * TT + t) * D;
            float* vcb = g_vc + ((size_t)(l * NB) * TT + t) * D;

            // ============ P1 qkv (buf0); pf o -> buf1
            pf_tile(p.ow + MO, D, srow0, scol, 32, buf1, pol);
            g_waitbar(bar);
            const float *x0, *x1;
            if (l == 0) {
                if (t == 0) {
                    if (tid < NB) stok[tid] = 0;
                } else if (tid < 64) {
                    int b = tid >> 5, lane = tid & 31;
                    unsigned long long m = 0ull;
                    for (int i = lane; i < NBLK; i += 32) {
                        unsigned long long v = __ldcg(&g_bmax[b * NBLK + i]);
                        if (v > m) m = v;
                    }
                    #pragma unroll
                    for (int o = 16; o; o >>= 1) {
                        unsigned long long v = __shfl_xor_sync(0xffffffffu, m, o);
                        if (v > m) m = v;
                    }
                    if (lane == 0) stok[b] = NV - 1 - (int)(m & 0xffffffffull);
                }
                __syncthreads();
                x0 = p.emb + (size_t)stok[0] * D;
                x1 = p.emb + (size_t)stok[1] * D;
            } else {
                x0 = g_x; x1 = g_x + D;
            }
            if (bx < 12) g_ff[bx * 512 + tid] = 0.f;   // zero ff (consumed prev P6)
            {
                float2 inv = rms_stage(x0, x1, part, sred);
                if (l == 0 && mat == 0 && (qrem & 7) == 0 && tid < 256) {
                    int b = tid >> 7, cc = tid & 127;
                    g_x[b * D + qcol * 128 + cc] = part[b * D + qcol * 128 + cc];
                }
                if (tid < 96) {
                    float wv = p.ln1[l * D + qrow0 + tid];
                    sh0[tid] = part[qrow0 + tid]     * inv.x * wv;
                    sh1[tid] = part[D + qrow0 + tid] * inv.y * wv;
                }
                __syncthreads();
                if (mat == 0)      gemv_dyn<96>(buf0, sh0, sh1, qcol, part, g_q, g_q + D);
                else if (mat == 1) gemv_dyn<96>(buf0, sh0, sh1, qcol, part, kcb, kcb + TT * D);
                else               gemv_dyn<96>(buf0, sh0, sh1, qcol, part, vcb, vcb + TT * D);
            }
            g_arrive(); ++bar;

            // ============ P2 self-attn (redundant, head hh) + o-proj (buf1); pf cq -> buf0
            pf_tile(p.cqw + MO, D, srow0, scol, 32, buf0, pol);
            g_waitbar(bar);
            {
                int n = t + 1;
                float* sq   = s;          // 128
                float* sp   = s + 128;    // 32
                float* se   = s + 160;    // 32
                float* ssum = s + 192;    // 2
                float* sv   = s + 256;    // 1024
                if (tid < 128) sq[tid] = __ldcg(&g_q[(tid >> 6) * D + hh * DKH + (tid & 63)]);
                for (int idx = tid; idx < NB * n * 32; idx += NTHR) {
                    int b = idx / (n * 32), r = idx % (n * 32), j = r >> 5, c = r & 31;
                    sv[(b * 16 + j) * 32 + c] =
                        __ldg(&g_vc[((size_t)(l * NB + b) * TT + j) * D + srow0 + c]);
                }
                __syncthreads();
                if (tid < 32) {
                    int b = tid >> 4, j = tid & 15;
                    if (j < n) {
                        const float4* kp4 = (const float4*)(g_kc +
                            ((size_t)(l * NB + b) * TT + j) * D + hh * DKH);
                        float sc = 0.f;
                        #pragma unroll
                        for (int d4 = 0; d4 < 16; d4++) {
                            float4 kv = __ldg(kp4 + d4);
                            sc += sq[b*64 + 4*d4]   * kv.x + sq[b*64 + 4*d4+1] * kv.y
                                + sq[b*64 + 4*d4+2] * kv.z + sq[b*64 + 4*d4+3] * kv.w;
                        }
                        sp[b * 16 + j] = sc + p.rb[(t - j) * NH + hh];
                    }
                }
                __syncthreads();
                if (tid < 2) {
                    float mx = -1e30f;
                    for (int j = 0; j < n; j++) mx = fmaxf(mx, sp[tid * 16 + j]);
                    float sum = 0.f;
                    for (int j = 0; j < n; j++) {
                        float e = __expf(sp[tid * 16 + j] - mx);
                        se[tid * 16 + j] = e; sum += e;
                    }
                    ssum[tid] = sum;
                }
                __syncthreads();
                if (tid < 64) {
                    int b = tid >> 5, c = tid & 31;
                    float acc = 0.f;
                    for (int j = 0; j < n; j++)
                        acc += se[b * 16 + j] * sv[(b * 16 + j) * 32 + c];
                    (b ? sh1 : sh0)[c] = acc / ssum[b];
                }
                gemv_dyn<32>(buf1, sh0, sh1, scol, part, g_x, g_x + D);
            }
            g_arrive(); ++bar;

            // ============ P3 cq (buf0); pf co -> buf1; zero g_q
            pf_tile(p.cow + MO, D, srow0, scol, 32, buf1, pol);
            g_waitbar(bar);
            if (bx < 3) g_q[bx * 512 + tid] = 0.f;
            {
                float2 inv = rms_stage(g_x, g_x + D, part, sred);
                if (tid < 32) {
                    float wv = p.ln2[l * D + srow0 + tid];
                    sh0[tid] = part[srow0 + tid]     * inv.x * wv;
                    sh1[tid] = part[D + srow0 + tid] * inv.y * wv;
                }
                __syncthreads();
                gemv_dyn<32>(buf0, sh0, sh1, scol, part, g_q2, g_q2 + D);
            }
            g_arrive(); ++bar;

            // ============ P4 cross-attn (redundant, head hh) + co-proj (buf1); pf wi -> buf0
            pf_tile(p.wi + (size_t)l * D * DFF, DFF, wirow0, wicol, 128, buf0, pol);
            g_waitbar(bar);
            {
                float* sq  = s;          // 128
                float* se  = s + 128;    // 512
                float* red = s + 640;    // 16
                float* sM  = s + 656;    // 2
                float* sS  = s + 658;    // 2
                float* pA  = s + 672;    // 512
                if (tid < 128) sq[tid] = __ldcg(&g_q2[(tid >> 6) * D + hh * DKH + (tid & 63)]);
                __syncthreads();
                int b = tid >> 8, pos = tid & 255;
                const float* kt = g_ckt + ((size_t)((l * NB + b) * NH + hh) * DKH) * ENCL;
                float sc = 0.f;
                #pragma unroll 16
                for (int d = 0; d < DKH; d++) sc += sq[b * 64 + d] * kt[(size_t)d * ENCL + pos];
                float m = sc;
                #pragma unroll
                for (int o = 16; o; o >>= 1) m = fmaxf(m, __shfl_xor_sync(0xffffffffu, m, o));
                if ((tid & 31) == 0) red[tid >> 5] = m;
                __syncthreads();
                if (tid < 2) {
                    float mm = red[tid * 8];
                    for (int w = 1; w < 8; w++) mm = fmaxf(mm, red[tid * 8 + w]);
                    sM[tid] = mm;
                }
                __syncthreads();
                float e = __expf(sc - sM[b]);
                se[tid] = e;
                float ss = e;
                #pragma unroll
                for (int o = 16; o; o >>= 1) ss += __shfl_xor_sync(0xffffffffu, ss, o);
                if ((tid & 31) == 0) red[tid >> 5] = ss;
                __syncthreads();
                if (tid < 2) {
                    float tt = 0.f;
                    for (int w = 0; w < 8; w++) tt += red[tid * 8 + w];
                    sS[tid] = tt;
                }
                __syncthreads();
                {
                    int c = pos & 31, grp = pos >> 5;
                    const float* vp = g_cv + (size_t)((l * NB + b) * ENCL) * D + srow0 + c;
                    float acc = 0.f;
                    for (int j = grp * 32; j < grp * 32 + 32; j++)
                        acc += se[b * 256 + j] * vp[(size_t)j * D];
                    pA[b * 256 + grp * 32 + c] = acc;
                }
                __syncthreads();
                if (tid < 64) {
                    int bb = tid >> 5, c = tid & 31;
                    float sum = 0.f;
                    #pragma unroll
                    for (int g = 0; g < 8; g++) sum += pA[bb * 256 + g * 32 + c];
                    (bb ? sh1 : sh0)[c] = sum / sS[bb];
                }
                gemv_dyn<32>(buf1, sh0, sh1, scol, part, g_x, g_x + D);
            }
            g_arrive(); ++bar;

            // ============ P5 wi (buf0); pf wo -> buf1; zero g_q2
            pf_tile(p.wo + (size_t)l * DFF * D, D, worow0, scol, 128, buf1, pol);
            g_waitbar(bar);
            if (bx < 3) g_q2[bx * 512 + tid] = 0.f;
            {
                float2 inv = rms_stage(g_x, g_x + D, part, sred);
                if (tid < 128) {
                    float wv = p.ln3[l * D + wirow0 + tid];
                    sh0[tid] = part[wirow0 + tid]     * inv.x * wv;
                    sh1[tid] = part[D + wirow0 + tid] * inv.y * wv;
                }
                __syncthreads();
                gemv_dyn<128>(buf0, sh0, sh1, wicol, part, g_ff, g_ff + DFF);
            }
            g_arrive(); ++bar;

            // ============ P6 wo (buf1); pf next qkv -> buf0
            {
                int nl = (l < NL - 1) ? l + 1 : 0;
                const float* W = (mat == 0 ? p.qw : (mat == 1 ? p.kw : p.vw)) + (size_t)nl * D * D;
                pf_tile(W, D, qrow0, qcol, 96, buf0, pol);
            }
            g_waitbar(bar);
            {
                if (tid < 128) {
                    sh0[tid] = fmaxf(__ldcg(&g_ff[worow0 + tid]), 0.f);
                    sh1[tid] = fmaxf(__ldcg(&g_ff[DFF + worow0 + tid]), 0.f);
                }
                __syncthreads();
                gemv_dyn<128>(buf1, sh0, sh1, scol, part, g_x, g_x + D);
            }
            g_arrive(); ++bar;
        }

        // ============ PL logits + per-block argmax (emb kept L2-resident)
        g_waitbar(bar);
        {
            float2 inv = rms_stage(g_x, g_x + D, part, sred);
            for (int i = tid; i < D; i += NTHR) {
                float w0 = p.fln[i] * RSQRT_D;
                part[i]     *= inv.x * w0;
                part[D + i] *= inv.y * w0;
            }
            __syncthreads();
            float* sx0 = part;
            float* sx1 = part + D;
            int warp = tid >> 5, lane = tid & 31;
            unsigned long long best0 = 0ull, best1 = 0ull;
            for (int v = bx * 16 + warp; v < NV; v += NBLK * 16) {
                const float4* e = (const float4*)(p.emb + (size_t)v * D);
                float a0 = 0.f, a1 = 0.f;
                #pragma unroll
                for (int i = lane; i < D / 4; i += 32) {
                    float4 w;
                    asm volatile("ld.global.nc.L2::cache_hint.v4.f32 {%0,%1,%2,%3}, [%4], %5;"
                                 : "=f"(w.x), "=f"(w.y), "=f"(w.z), "=f"(w.w)
                                 : "l"(e + i), "l"(polL));
                    a0 += w.x * sx0[4*i] + w.y * sx0[4*i+1] + w.z * sx0[4*i+2] + w.w * sx0[4*i+3];
                    a1 += w.x * sx1[4*i] + w.y * sx1[4*i+1] + w.z * sx1[4*i+2] + w.w * sx1[4*i+3];
                }
                #pragma unroll
                for (int o = 16; o; o >>= 1) {
                    a0 += __shfl_xor_sync(0xffffffffu, a0, o);
                    a1 += __shfl_xor_sync(0xffffffffu, a1, o);
                }
                if (lane == 0) {
                    __stcs(&p.out[((size_t)0 * TT + t) * NV + v], a0);
                    __stcs(&p.out[((size_t)1 * TT + t) * NV + v], a1);
                    unsigned b0 = __float_as_uint(a0);
                    unsigned b1 = __float_as_uint(a1);
                    unsigned u0 = (b0 & 0x80000000u) ? ~b0 : (b0 | 0x80000000u);
                    unsigned u1 = (b1 & 0x80000000u) ? ~b1 : (b1 | 0x80000000u);
                    unsigned long long k0 = ((unsigned long long)u0 << 32) | (unsigned)(NV - 1 - v);
                    unsigned long long k1 = ((unsigned long long)u1 << 32) | (unsigned)(NV - 1 - v);
                    if (k0 > best0) best0 = k0;
                    if (k1 > best1) best1 = k1;
                }
            }
            if (lane == 0) { sb[warp] = best0; sb[16 + warp] = best1; }
            __syncthreads();
            if (tid < 2) {
                unsigned long long m = 0ull;
                #pragma unroll
                for (int w = 0; w < 16; w++) {
                    unsigned long long v = sb[tid * 16 + w];
                    if (v > m) m = v;
                }
                g_bmax[tid * NBLK + bx] = m;
            }
        }
        g_arrive(); ++bar;
    }
    asm volatile("cp.async.wait_group 0;" ::: "memory");
}

// ------------------------------------------------------------------ cross K/V precompute (3 cols/thread, FMA-dense)
__global__ __launch_bounds__(256) void k_cross_kv(
    const float* __restrict__ enc, const float* __restrict__ ckw,
    const float* __restrict__ cvw)
{
    __shared__ float sx[8][D];                // 24KB
    if (blockIdx.x == 0 && threadIdx.x == 0) g_cnt = 0;   // barrier reset for k_decode
    int bx = blockIdx.x;                      // 512 blocks = rowblk(64) x mat(2) x layer(4)
    int rb  = bx % 64; bx /= 64;
    int mat = bx % 2;
    int l   = bx / 2;
    int row0 = rb * 8;
    for (int i = threadIdx.x; i < 8 * D; i += 256)
        sx[i / D][i % D] = enc[(size_t)row0 * D + i];
    __syncthreads();
    const float* W = (mat == 0 ? ckw : cvw) + (size_t)l * D * D;
    int col = threadIdx.x;
    float acc[8][3];
    #pragma unroll
    for (int r = 0; r < 8; r++)
        #pragma unroll
        for (int cc = 0; cc < 3; cc++) acc[r][cc] = 0.f;
    const float* Wp = W + col;
    #pragma unroll 4
    for (int i = 0; i < D; i++) {
        const float* wrow = Wp + (size_t)i * D;
        float w0 = wrow[0], w1 = wrow[256], w2 = wrow[512];
        #pragma unroll
        for (int r = 0; r < 8; r++) {
            float a = sx[r][i];
            acc[r][0] += a * w0; acc[r][1] += a * w1; acc[r][2] += a * w2;
        }
    }
    #pragma unroll
    for (int cc = 0; cc < 3; cc++) {
        int c = col + cc * 256;
        int h = c / DKH, dd = c % DKH;
        for (int r = 0; r < 8; r++) {
            int g = row0 + r; int b = g / ENCL; int pnum = g % ENCL;
            if (mat == 0)
                g_ckt[(((size_t)(l * NB + b) * NH + h) * DKH + dd) * ENCL + pnum] = acc[r][cc];
            else
                g_cv[((size_t)(l * NB + b) * ENCL + pnum) * D + c] = acc[r][cc];
        }
    }
}

// ------------------------------------------------------------------ launch
extern "C" void kernel_launch(void* const* d_in, const int* in_sizes, int n_in,
                              void* d_out, int out_size) {
    Params p;
    const float* enc = (const float*)d_in[0];
    p.emb = (const float*)d_in[1];
    p.ln1 = (const float*)d_in[2];
    p.qw  = (const float*)d_in[3];
    p.kw  = (const float*)d_in[4];
    p.vw  = (const float*)d_in[5];
    p.ow  = (const float*)d_in[6];
    p.ln2 = (const float*)d_in[7];
    p.cqw = (const float*)d_in[8];
    const float* ckw = (const float*)d_in[9];
    const float* cvw = (const float*)d_in[10];
    p.cow = (const float*)d_in[11];
    p.ln3 = (const float*)d_in[12];
    p.wi  = (const float*)d_in[13];
    p.wo  = (const float*)d_in[14];
    p.fln = (const float*)d_in[15];
    p.rb  = (const float*)d_in[16];
    p.out = (float*)d_out;

    static int smem_set = 0;
    if (!smem_set) {
        cudaFuncSetAttribute(k_decode, cudaFuncAttributeMaxDynamicSharedMemorySize, 131072);
        smem_set = 1;
    }

    k_cross_kv<<<512, 256>>>(enc, ckw, cvw);
    k_decode<<<NBLK, NTHR, 131072>>>(p);
}